// round 17
// baseline (speedup 1.0000x reference)
#include <cuda_runtime.h>
#include <cuda_fp16.h>
#include <cstdint>

// Problem constants
#define P_DIM 64
#define B_DIM 256
#define H_DIM 512
#define IN_DIM 2
#define PB (P_DIM * B_DIM)      // 16384 fused batch rows

// Tiling (fp16 operands, mbarrier free-running pipeline)
#define MT 128                  // rows per CTA
#define HT 32                   // h-columns per CTA (x4 gates -> 128 N cols)
#define KTH 64                  // k (halves) per pipeline stage = 128B rows
#define NSTAGE 3
#define PITCH_B 144             // bytes per smem row (72 halves) -> conflict-free LDSM
#define A_STAGE_B (128 * PITCH_B)
#define STAGE_B (2 * A_STAGE_B)            // A + B tiles: 36864 B
#define OFF_FULL  (NSTAGE * STAGE_B)       // 110592
#define OFF_EMPTY (OFF_FULL + NSTAGE * 8)
#define SMEM_TOTAL (OFF_EMPTY + NSTAGE * 8 + 16)

// fp16 scratch (device globals: allocation-free)
__device__ __half g_h0h[(size_t)P_DIM * 2 * B_DIM * H_DIM];   // h0 converted
__device__ __half g_h1h[(size_t)PB * H_DIM];                  // layer-0 output
__device__ __half g_w16[3][2048 * 512];                       // w_hh0, w_ih1, w_hh1

__device__ __forceinline__ void cpa16(unsigned saddr, const __half* g) {
    asm volatile("cp.async.cg.shared.global [%0], [%1], 16;\n" :: "r"(saddr), "l"(g));
}
__device__ __forceinline__ void mbar_init(uint32_t a, uint32_t n) {
    asm volatile("mbarrier.init.shared.b64 [%0], %1;" :: "r"(a), "r"(n) : "memory");
}
__device__ __forceinline__ void mbar_wait(uint32_t a, uint32_t par) {
    asm volatile(
        "{\n\t.reg .pred P;\n"
        "WL%=:\n\t"
        "mbarrier.try_wait.parity.shared.b64 P, [%0], %1;\n\t"
        "@!P bra WL%=;\n\t"
        "}" :: "r"(a), "r"(par) : "memory");
}
__device__ __forceinline__ void mbar_arrive(uint32_t a) {
    asm volatile("mbarrier.arrive.shared.b64 _, [%0];" :: "r"(a) : "memory");
}
__device__ __forceinline__ void cpasync_arrive(uint32_t a) {
    asm volatile("cp.async.mbarrier.arrive.noinc.shared.b64 [%0];" :: "r"(a) : "memory");
}

// ldmatrix x4: 4 8x8 b16 matrices
__device__ __forceinline__ void ldsm4(uint32_t* r, uint32_t addr) {
    asm volatile("ldmatrix.sync.aligned.m8n8.x4.shared.b16 {%0,%1,%2,%3}, [%4];"
                 : "=r"(r[0]), "=r"(r[1]), "=r"(r[2]), "=r"(r[3]) : "r"(addr));
}

__device__ __forceinline__ void mma_f16(float* c, const uint32_t* a,
                                        uint32_t b0, uint32_t b1) {
    asm volatile(
        "mma.sync.aligned.m16n8k16.row.col.f32.f16.f16.f32 "
        "{%0,%1,%2,%3}, {%4,%5,%6,%7}, {%8,%9}, {%0,%1,%2,%3};\n"
        : "+f"(c[0]), "+f"(c[1]), "+f"(c[2]), "+f"(c[3])
        : "r"(a[0]), "r"(a[1]), "r"(a[2]), "r"(a[3]), "r"(b0), "r"(b1));
}

__device__ __forceinline__ float tanh_fast(float x) {
    float y;
    asm("tanh.approx.f32 %0, %1;" : "=f"(y) : "f"(x));
    return y;
}
__device__ __forceinline__ float sigmoid_fast(float x) {
    return fmaf(tanh_fast(0.5f * x), 0.5f, 0.5f);
}

// -------- conversion prologue: h0 + 3 weight matrices -> fp16 --------
__global__ void cvt_all_kernel(const float4* __restrict__ h0,
                               const float4* __restrict__ w0,
                               const float4* __restrict__ w1,
                               const float4* __restrict__ w2) {
    const size_t nh = (size_t)P_DIM * 2 * B_DIM * H_DIM / 4;
    const size_t nw = (size_t)2048 * 512 / 4;
    const size_t total = nh + 3 * nw;
    const size_t stride = (size_t)gridDim.x * blockDim.x;
    for (size_t i0 = (size_t)blockIdx.x * blockDim.x + threadIdx.x; i0 < total;
         i0 += 4 * stride) {
        float4 v[4]; __half2* dp[4]; size_t jj[4]; int nv = 0;
#pragma unroll
        for (int u = 0; u < 4; u++) {
            const size_t i = i0 + u * stride;
            if (i >= total) break;
            const float4* src; __half2* dst; size_t j;
            if (i < nh) { src = h0; dst = (__half2*)g_h0h; j = i; }
            else {
                const size_t k = i - nh;
                const int sel = (int)(k / nw);
                j = k - (size_t)sel * nw;
                src = (sel == 0) ? w0 : (sel == 1) ? w1 : w2;
                dst = (__half2*)g_w16[sel];
            }
            v[u] = src[j]; dp[u] = dst; jj[u] = j; nv = u + 1;
        }
#pragma unroll
        for (int u = 0; u < 4; u++) {
            if (u >= nv) break;
            dp[u][2 * jj[u]]     = __floats2half2_rn(v[u].x, v[u].y);
            dp[u][2 * jj[u] + 1] = __floats2half2_rn(v[u].z, v[u].w);
        }
    }
}

// One LSTM layer, fused GEMM (fp16 mma, fp32 accum) + register-resident cell.
// Output-column permutation: smem B row n = wn*64 + nt*8 + 2*t4 + e holds weight
// row gate*512 + hBase + j with gate = e + 2*(nt&1), j = wn*16 + t4 + 4*(nt>>1).
// => each thread's acc fragment holds all 4 gates for 4 j values: cell in regs.
template <int LAYER>
__global__ void __launch_bounds__(256, 2)
lstm_layer_kernel(const float* __restrict__ x_in,
                  const float* __restrict__ c0,
                  const float* __restrict__ w_ih0,
                  const float* __restrict__ b_ih,
                  const float* __restrict__ b_hh,
                  float* __restrict__ d_out) {
    extern __shared__ float smem[];

    const int tid  = threadIdx.x;
    const int warp = tid >> 5;
    const int lane = tid & 31;
    const int wm = warp >> 1;          // 0..3 : 32-row slab
    const int wn = warp & 1;           // 0..1 : 64-col half
    const int rowW = wm * 32;
    const int colW = wn * 64;

    const int mTile = blockIdx.y;      // 0..127
    const int hTile = blockIdx.x;      // 0..15
    const int rowBase = mTile * MT;
    const int hBase   = hTile * HT;

    const int p0 = rowBase >> 8;       // row = p*256 + b
    const int b0 = rowBase & 255;

    const __half* Ab0 = (LAYER == 0)
        ? g_h0h + ((size_t)(p0 * 2 + 0) * B_DIM + b0) * H_DIM
        : g_h1h + (size_t)rowBase * H_DIM;
    const __half* Ab1 = g_h0h + ((size_t)(p0 * 2 + 1) * B_DIM + b0) * H_DIM;
    const __half* Wb0 = (LAYER == 0) ? g_w16[0] : g_w16[1];
    const __half* Wb1 = g_w16[2];

    const int KTILES = (LAYER == 0) ? 8 : 16;   // K/64

    const unsigned smem_u = (unsigned)__cvta_generic_to_shared(smem);
    const uint32_t mb_full  = smem_u + OFF_FULL;
    const uint32_t mb_empty = smem_u + OFF_EMPTY;

    if (tid == 0) {
#pragma unroll
        for (int s = 0; s < NSTAGE; s++) {
            mbar_init(mb_full  + s * 8, 256);
            mbar_init(mb_empty + s * 8, 8);
        }
    }
    __syncthreads();

    // -------- stage loader: A [128 x 64h], B [128(permuted) x 64h] --------
    auto load_stage = [&](int kt) {
        int s = kt; while (s >= NSTAGE) s -= NSTAGE;
        const int ip = kt / NSTAGE;
        if (ip >= 1) mbar_wait(mb_empty + s * 8, (uint32_t)((ip + 1) & 1));
        const __half* Ab = (LAYER == 0 || kt < 8) ? Ab0 : Ab1;
        const __half* Wb = (LAYER == 0 || kt < 8) ? Wb0 : Wb1;
        const int kk = (kt & 7) * KTH;
        const unsigned Asd = smem_u + (unsigned)(s * STAGE_B);
        const unsigned Bsd = Asd + (unsigned)A_STAGE_B;
#pragma unroll
        for (int i = 0; i < 4; i++) {
            const int c  = tid + i * 256;       // 0..1023 : 16B chunks
            const int r  = c >> 3;              // 0..127
            const int cc = c & 7;               // chunk within row
            cpa16(Asd + (unsigned)(r * PITCH_B + cc * 16),
                  Ab + (size_t)r * H_DIM + kk + cc * 8);
            // permuted B row mapping
            const int wn_ = r >> 6, rem = r & 63;
            const int nt = rem >> 3, t4 = (rem >> 1) & 3, e = rem & 1;
            const int gate = e + 2 * (nt & 1);
            const int jcol = wn_ * 16 + t4 + 4 * (nt >> 1);
            cpa16(Bsd + (unsigned)(r * PITCH_B + cc * 16),
                  Wb + (size_t)(gate * H_DIM + hBase + jcol) * H_DIM + kk + cc * 8);
        }
        cpasync_arrive(mb_full + s * 8);
    };

    float acc[2][8][4];
#pragma unroll
    for (int mi = 0; mi < 2; mi++)
#pragma unroll
        for (int nt = 0; nt < 8; nt++)
#pragma unroll
            for (int q = 0; q < 4; q++) acc[mi][nt][q] = 0.0f;

    // -------- per-thread LDSM base offsets (bytes) --------
    const int m8 = lane >> 3;
    const int l8 = lane & 7;
    const uint32_t aoff =
        (uint32_t)((rowW + (m8 & 1) * 8 + l8) * PITCH_B + (m8 >> 1) * 16);
    uint32_t boff[4];
#pragma unroll
    for (int t = 0; t < 4; t++)
        boff[t] = (uint32_t)((colW + (t * 2 + (m8 >> 1)) * 8 + l8) * PITCH_B
                             + (m8 & 1) * 16);

    // -------- mainloop: free-running mbarrier pipeline (no CTA barrier) --------
    load_stage(0);
    load_stage(1);

    int s = 0;
    for (int kt = 0; kt < KTILES; kt++) {
        const int cyc = kt / NSTAGE;
        mbar_wait(mb_full + s * 8, (uint32_t)(cyc & 1));

        const uint32_t As = smem_u + (uint32_t)(s * STAGE_B);
        const uint32_t Bs = As + (uint32_t)A_STAGE_B;

        uint32_t afr[2][8], bfr[2][4];
        ldsm4(&afr[0][0], As + aoff);
        ldsm4(&afr[0][4], As + aoff + (uint32_t)(16 * PITCH_B));
        ldsm4(bfr[0], Bs + boff[0]);

        int cur = 0;
#pragma unroll
        for (int k0 = 0; k0 < 4; k0++) {
#pragma unroll
            for (int t = 0; t < 4; t++) {
                if (t < 3) {
                    ldsm4(bfr[(t + 1) & 1], Bs + boff[t + 1] + k0 * 32);
                } else if (k0 < 3) {
                    ldsm4(&afr[cur ^ 1][0], As + aoff + (k0 + 1) * 32);
                    ldsm4(&afr[cur ^ 1][4],
                          As + aoff + (uint32_t)(16 * PITCH_B) + (k0 + 1) * 32);
                    ldsm4(bfr[0], Bs + boff[0] + (k0 + 1) * 32);
                }
                // early empty-arrive: all smem reads of this stage are done
                if (k0 == 3 && t == 3 && lane == 0) mbar_arrive(mb_empty + s * 8);
                const uint32_t* b = bfr[t & 1];
                mma_f16(acc[0][2 * t],     &afr[cur][0], b[0], b[1]);
                mma_f16(acc[1][2 * t],     &afr[cur][4], b[0], b[1]);
                mma_f16(acc[0][2 * t + 1], &afr[cur][0], b[2], b[3]);
                mma_f16(acc[1][2 * t + 1], &afr[cur][4], b[2], b[3]);
            }
            cur ^= 1;
        }

        if (kt + 2 < KTILES) load_stage(kt + 2);
        if (++s == NSTAGE) s = 0;
    }

    // -------- register-resident LSTM cell + stores (no smem roundtrip) --------
    const size_t hn_off = (size_t)PB * H_DIM;
    const size_t cn_off = hn_off + (size_t)P_DIM * 2 * B_DIM * H_DIM;

    const int t4 = lane & 3;
    const int r0 = lane >> 2;

    // per-thread h values: h[jj] = hBase + wn*16 + t4 + 4*jj
    float bia[4][4];   // [jj][gate] combined biases
    float wxa[4][4][2];
#pragma unroll
    for (int jj = 0; jj < 4; jj++) {
        const int h = hBase + wn * 16 + t4 + 4 * jj;
#pragma unroll
        for (int g = 0; g < 4; g++) {
            const int wrow = g * H_DIM + h;
            bia[jj][g] = b_ih[wrow] + b_hh[wrow];
            if (LAYER == 0) {
                wxa[jj][g][0] = w_ih0[(size_t)wrow * 2];
                wxa[jj][g][1] = w_ih0[(size_t)wrow * 2 + 1];
            }
        }
    }

#pragma unroll
    for (int mi = 0; mi < 2; mi++) {
#pragma unroll
        for (int rr = 0; rr < 2; rr++) {
            const int row = rowBase + rowW + mi * 16 + r0 + rr * 8;
            const int p   = row >> 8;
            const int b   = row & 255;
            float x0 = 0.f, x1 = 0.f;
            if (LAYER == 0) {
                x0 = x_in[(size_t)(b * P_DIM + p) * IN_DIM];
                x1 = x_in[(size_t)(b * P_DIM + p) * IN_DIM + 1];
            }
#pragma unroll
            for (int jj = 0; jj < 4; jj++) {
                const int h = hBase + wn * 16 + t4 + 4 * jj;
                float gi = acc[mi][2 * jj][rr * 2]         + bia[jj][0];
                float gf = acc[mi][2 * jj][rr * 2 + 1]     + bia[jj][1];
                float gg = acc[mi][2 * jj + 1][rr * 2]     + bia[jj][2];
                float go = acc[mi][2 * jj + 1][rr * 2 + 1] + bia[jj][3];
                if (LAYER == 0) {
                    gi += x0 * wxa[jj][0][0] + x1 * wxa[jj][0][1];
                    gf += x0 * wxa[jj][1][0] + x1 * wxa[jj][1][1];
                    gg += x0 * wxa[jj][2][0] + x1 * wxa[jj][2][1];
                    go += x0 * wxa[jj][3][0] + x1 * wxa[jj][3][1];
                }
                const float i_s = sigmoid_fast(gi);
                const float f_s = sigmoid_fast(gf);
                const float o_s = sigmoid_fast(go);
                const float g_t = tanh_fast(gg);

                const size_t cidx =
                    (((size_t)p * 2 + LAYER) * B_DIM + b) * H_DIM + h;
                const float c_new = f_s * c0[cidx] + i_s * g_t;
                const float h_new = o_s * tanh_fast(c_new);

                d_out[hn_off + cidx] = h_new;
                d_out[cn_off + cidx] = c_new;
                if (LAYER == 0) {
                    g_h1h[(size_t)row * H_DIM + h] = __float2half_rn(h_new);
                } else {
                    d_out[((size_t)b * P_DIM + p) * H_DIM + h] = h_new;
                }
            }
        }
    }
}

extern "C" void kernel_launch(void* const* d_in, const int* in_sizes, int n_in,
                              void* d_out, int out_size) {
    const float* x     = (const float*)d_in[0];   // input_traces [B,P,2]
    const float* h0    = (const float*)d_in[1];   // [P,L,B,H]
    const float* c0    = (const float*)d_in[2];   // [P,L,B,H]
    const float* w_ih0 = (const float*)d_in[3];   // [2048,2]
    const float* w_hh0 = (const float*)d_in[4];   // [2048,512]
    const float* b_ih0 = (const float*)d_in[5];
    const float* b_hh0 = (const float*)d_in[6];
    const float* w_ih1 = (const float*)d_in[7];   // [2048,512]
    const float* w_hh1 = (const float*)d_in[8];   // [2048,512]
    const float* b_ih1 = (const float*)d_in[9];
    const float* b_hh1 = (const float*)d_in[10];
    float* out = (float*)d_out;

    cvt_all_kernel<<<2048, 256>>>((const float4*)h0, (const float4*)w_hh0,
                                  (const float4*)w_ih1, (const float4*)w_hh1);

    cudaFuncSetAttribute(lstm_layer_kernel<0>,
                         cudaFuncAttributeMaxDynamicSharedMemorySize, SMEM_TOTAL);
    cudaFuncSetAttribute(lstm_layer_kernel<1>,
                         cudaFuncAttributeMaxDynamicSharedMemorySize, SMEM_TOTAL);

    dim3 grid(H_DIM / HT, PB / MT);               // (16, 128)
    lstm_layer_kernel<0><<<grid, 256, SMEM_TOTAL>>>(x, c0, w_ih0, b_ih0, b_hh0, out);
    lstm_layer_kernel<1><<<grid, 256, SMEM_TOTAL>>>(nullptr, c0, nullptr,
                                                    b_ih1, b_hh1, out);
}